// round 1
// baseline (speedup 1.0000x reference)
#include <cuda_runtime.h>

#define BB 64
#define NP 576
#define DD 512
#define MM 16

__device__ float  g_scaled[BB*MM*NP];   // sim / T
__device__ float  g_scores[BB*BB];
__device__ double g_accs[2];            // [0]=contrast sum, [1]=mask sum

// ---------------- packed f32x2 helpers ----------------
__device__ __forceinline__ void fma2(unsigned long long &acc, unsigned long long a, unsigned long long b){
    asm("fma.rn.f32x2 %0, %1, %2, %0;" : "+l"(acc) : "l"(a), "l"(b));
}
__device__ __forceinline__ float unpack_sum(unsigned long long a){
    float lo, hi;
    asm("mov.b64 {%0,%1}, %2;" : "=f"(lo), "=f"(hi) : "l"(a));
    return lo + hi;
}

// ---------------- top-5 helpers ----------------
__device__ __forceinline__ void top5_insert(float t[5], float a){
    #pragma unroll
    for (int q = 0; q < 5; ++q){
        float mx = fmaxf(t[q], a);
        a        = fminf(t[q], a);
        t[q] = mx;
    }
}
// Merge per-lane sorted top-5 lists across a warp: 5 rounds of warp argmax + pop.
// Returns the sum of the warp-wide top-5. If write5 != nullptr, lane0 writes the
// 5 values there (descending).
__device__ __forceinline__ float warp_top5_sum(float t[5], int lane, float* write5){
    float total = 0.0f;
    #pragma unroll
    for (int it = 0; it < 5; ++it){
        float v = t[0]; int who = lane;
        #pragma unroll
        for (int d = 16; d >= 1; d >>= 1){
            float ov = __shfl_xor_sync(0xffffffffu, v,   d);
            int   ow = __shfl_xor_sync(0xffffffffu, who, d);
            if (ov > v || (ov == v && ow < who)){ v = ov; who = ow; }
        }
        total += v;
        if (write5 && lane == 0) write5[it] = v;
        if (lane == who){ t[0]=t[1]; t[1]=t[2]; t[2]=t[3]; t[3]=t[4]; t[4]=-1e30f; }
    }
    return total;
}

// =======================================================================
// Kernel 1: sim[b,m,n]/T  (grid (9,64), 256 threads)
// Per warp: 8 patches in 2 groups of 4, full K=512 dot vs 16 nouns.
// =======================================================================
__global__ __launch_bounds__(256, 1)
void k_sim(const float* __restrict__ patch, const float* __restrict__ noun){
    __shared__ ulonglong2 noun_s[MM * DD / 4];   // 32 KB, [m][f4idx]

    const int b = blockIdx.y;
    // block (0,0) thread 0 also zeroes the accumulators (runs before k_fine)
    if (blockIdx.x == 0 && blockIdx.y == 0 && threadIdx.x == 0){
        g_accs[0] = 0.0; g_accs[1] = 0.0;
    }

    const ulonglong2* np = reinterpret_cast<const ulonglong2*>(noun + (size_t)b * MM * DD);
    for (int i = threadIdx.x; i < MM * DD / 4; i += 256) noun_s[i] = np[i];
    __syncthreads();

    const int lane = threadIdx.x & 31;
    const int warp = threadIdx.x >> 5;
    const float INVT = (float)(1.0 / 0.07);

    for (int g = 0; g < 2; ++g){
        const int n0 = blockIdx.x * 64 + warp * 8 + g * 4;
        unsigned long long acc[4][16];
        #pragma unroll
        for (int p = 0; p < 4; ++p)
            #pragma unroll
            for (int m = 0; m < 16; ++m) acc[p][m] = 0ull;

        const ulonglong2* pb =
            reinterpret_cast<const ulonglong2*>(patch) + ((size_t)b * NP + n0) * (DD / 4);

        #pragma unroll
        for (int j = 0; j < 4; ++j){
            ulonglong2 pf[4];
            #pragma unroll
            for (int p = 0; p < 4; ++p) pf[p] = pb[p * (DD/4) + lane + 32 * j];
            #pragma unroll
            for (int m = 0; m < 16; ++m){
                ulonglong2 nf = noun_s[m * (DD/4) + lane + 32 * j];
                #pragma unroll
                for (int p = 0; p < 4; ++p){
                    fma2(acc[p][m], pf[p].x, nf.x);
                    fma2(acc[p][m], pf[p].y, nf.y);
                }
            }
        }

        // 64 per-lane partials -> 64 warp sums, multi-value butterfly (62 shfl)
        float v[64];
        #pragma unroll
        for (int p = 0; p < 4; ++p)
            #pragma unroll
            for (int m = 0; m < 16; ++m) v[p*16 + m] = unpack_sum(acc[p][m]);

        float w32[32];
        #pragma unroll
        for (int i = 0; i < 32; ++i){
            float send = (lane & 16) ? v[i] : v[i+32];
            float recv = __shfl_xor_sync(0xffffffffu, send, 16);
            w32[i] = ((lane & 16) ? v[i+32] : v[i]) + recv;
        }
        float w16[16];
        #pragma unroll
        for (int i = 0; i < 16; ++i){
            float send = (lane & 8) ? w32[i] : w32[i+16];
            float recv = __shfl_xor_sync(0xffffffffu, send, 8);
            w16[i] = ((lane & 8) ? w32[i+16] : w32[i]) + recv;
        }
        float w8[8];
        #pragma unroll
        for (int i = 0; i < 8; ++i){
            float send = (lane & 4) ? w16[i] : w16[i+8];
            float recv = __shfl_xor_sync(0xffffffffu, send, 4);
            w8[i] = ((lane & 4) ? w16[i+8] : w16[i]) + recv;
        }
        float w4[4];
        #pragma unroll
        for (int i = 0; i < 4; ++i){
            float send = (lane & 2) ? w8[i] : w8[i+4];
            float recv = __shfl_xor_sync(0xffffffffu, send, 2);
            w4[i] = ((lane & 2) ? w8[i+4] : w8[i]) + recv;
        }
        float w2[2];
        #pragma unroll
        for (int i = 0; i < 2; ++i){
            float send = (lane & 1) ? w4[i] : w4[i+2];
            float recv = __shfl_xor_sync(0xffffffffu, send, 1);
            w2[i] = ((lane & 1) ? w4[i+2] : w4[i]) + recv;
        }
        // lane holds outputs o = 2*lane + j ; o = p*16 + m
        #pragma unroll
        for (int j2 = 0; j2 < 2; ++j2){
            int o = 2 * lane + j2;
            int p = o >> 4, m = o & 15;
            g_scaled[((size_t)b * MM + m) * NP + n0 + p] = w2[j2] * INVT;
        }
    }
}

// =======================================================================
// Kernel 2: fine-grained reductions (grid 64, 512 threads = 16 warps)
// =======================================================================
__global__ __launch_bounds__(512)
void k_fine(){
    const int b    = blockIdx.x;
    const int lane = threadIdx.x & 31;
    const int w    = threadIdx.x >> 5;

    __shared__ float s_sp[16];
    __shared__ float s_top[16 * 5];

    // ---- part A: per-noun (m = w) lse + top5 ----
    const float* row = g_scaled + ((size_t)b * MM + w) * NP;
    float t[5] = {-1e30f, -1e30f, -1e30f, -1e30f, -1e30f};
    for (int i = lane; i < NP; i += 32) top5_insert(t, row[i]);

    float MX = t[0];
    #pragma unroll
    for (int d = 16; d >= 1; d >>= 1) MX = fmaxf(MX, __shfl_xor_sync(0xffffffffu, MX, d));

    float se = 0.0f;
    for (int i = lane; i < NP; i += 32) se += expf(row[i] - MX);
    #pragma unroll
    for (int d = 16; d >= 1; d >>= 1) se += __shfl_xor_sync(0xffffffffu, se, d);

    float tsum = warp_top5_sum(t, lane, nullptr);
    if (lane == 0){
        float lse = MX + logf(se);
        atomicAdd(&g_accs[0], (double)(5.0f * lse - tsum));
    }

    // ---- part B: pooled x, softplus sum, block top-5 ----
    float u[5] = {-1e30f, -1e30f, -1e30f, -1e30f, -1e30f};
    float sp = 0.0f;
    const float* base = g_scaled + (size_t)b * MM * NP;
    #pragma unroll
    for (int rep = 0; rep < 2; ++rep){
        int n = threadIdx.x + rep * 512;
        if (n < NP){
            float s = 0.0f;
            #pragma unroll
            for (int m = 0; m < 16; ++m) s += base[m * NP + n];
            float x = s * (1.0f / 16.0f);
            sp += fmaxf(x, 0.0f) + log1pf(expf(-fabsf(x)));
            top5_insert(u, x);
        }
    }
    #pragma unroll
    for (int d = 16; d >= 1; d >>= 1) sp += __shfl_xor_sync(0xffffffffu, sp, d);
    if (lane == 0) s_sp[w] = sp;

    warp_top5_sum(u, lane, &s_top[w * 5]);   // lane0 writes warp's top5
    __syncthreads();

    if (w == 0){
        float q[5] = {-1e30f, -1e30f, -1e30f, -1e30f, -1e30f};
        for (int i = lane; i < 80; i += 32) top5_insert(q, s_top[i]);
        float fsum = warp_top5_sum(q, lane, nullptr);

        float tot = (lane < 16) ? s_sp[lane] : 0.0f;
        #pragma unroll
        for (int d = 16; d >= 1; d >>= 1) tot += __shfl_xor_sync(0xffffffffu, tot, d);

        if (lane == 0) atomicAdd(&g_accs[1], (double)(tot - fsum));
    }
}

// =======================================================================
// Kernel 3: scores = img @ txt^T  (grid 64 rows, 256 threads)
// =======================================================================
__device__ __forceinline__ float dot4(float4 a, float4 b){
    return a.x*b.x + a.y*b.y + a.z*b.z + a.w*b.w;
}
__global__ __launch_bounds__(256)
void k_scores(const float* __restrict__ img, const float* __restrict__ txt){
    const int i    = blockIdx.x;
    const int lane = threadIdx.x & 31;
    const int w    = threadIdx.x >> 5;
    const float4* ip = reinterpret_cast<const float4*>(img + (size_t)i * DD);
    float4 a0 = ip[lane], a1 = ip[lane+32], a2 = ip[lane+64], a3 = ip[lane+96];
    for (int tj = 0; tj < 8; ++tj){
        int j = w * 8 + tj;
        const float4* tp = reinterpret_cast<const float4*>(txt + (size_t)j * DD);
        float s = dot4(a0, tp[lane]) + dot4(a1, tp[lane+32])
                + dot4(a2, tp[lane+64]) + dot4(a3, tp[lane+96]);
        #pragma unroll
        for (int d = 16; d >= 1; d >>= 1) s += __shfl_xor_sync(0xffffffffu, s, d);
        if (lane == 0) g_scores[i * BB + j] = s;
    }
}

// =======================================================================
// Kernel 4: contrastive + triplet losses, final combine (1 block, 256 thr)
// =======================================================================
__global__ __launch_bounds__(256)
void k_final(const float* __restrict__ logit_scale, const int* __restrict__ idx,
             float* __restrict__ out){
    __shared__ float sc[64][65];
    __shared__ float diag[64];
    __shared__ int   sidx[64];
    __shared__ float red[256];
    const int tid = threadIdx.x;

    for (int e = tid; e < 4096; e += 256) sc[e >> 6][e & 63] = g_scores[e];
    if (tid < 64) sidx[tid] = idx[tid];
    __syncthreads();
    if (tid < 64) diag[tid] = sc[tid][tid];
    __syncthreads();

    const float s = logit_scale[0];

    float myc = 0.0f;
    if (tid < 64){
        const int i = tid, myid = sidx[i];
        // row log-softmax
        float mx = -1e30f;
        for (int j = 0; j < 64; ++j) mx = fmaxf(mx, sc[i][j]);
        float se = 0.0f, msum = 0.0f; int cnt = 0;
        for (int j = 0; j < 64; ++j){
            float l = s * sc[i][j];
            se += expf(l - s * mx);
            if (sidx[j] == myid){ msum += l; ++cnt; }
        }
        float li2t = (s * mx + logf(se)) - msum / (float)cnt;
        // column log-softmax
        float mxc = -1e30f;
        for (int j = 0; j < 64; ++j) mxc = fmaxf(mxc, sc[j][i]);
        float sec = 0.0f, csum = 0.0f;
        for (int j = 0; j < 64; ++j){
            float l = s * sc[j][i];
            sec += expf(l - s * mxc);
            if (sidx[j] == myid) csum += l;
        }
        float lt2i = (s * mxc + logf(sec)) - csum / (float)cnt;
        myc = 0.5f * (li2t + lt2i);
    }
    red[tid] = myc;
    __syncthreads();
    for (int st = 128; st > 0; st >>= 1){
        if (tid < st) red[tid] += red[tid + st];
        __syncthreads();
    }
    float loss_c = red[0] / 64.0f;
    __syncthreads();

    // triplet
    float mt = 0.0f;
    for (int e = tid; e < 4096; e += 256){
        int i = e >> 6, j = e & 63;
        if (i != j){
            float v = sc[i][j];
            mt += fmaxf(0.0f, 0.1f + v - diag[i]) + fmaxf(0.0f, 0.1f + v - diag[j]);
        }
    }
    red[tid] = mt;
    __syncthreads();
    for (int st = 128; st > 0; st >>= 1){
        if (tid < st) red[tid] += red[tid + st];
        __syncthreads();
    }
    if (tid == 0){
        out[0] = loss_c;
        out[1] = 0.5f * red[0];
        double contrast = g_accs[0] / (double)(BB * MM);
        double mask     = g_accs[1] / (double)(BB * NP);
        out[2] = (float)(0.6 * contrast + 0.4 * mask);
    }
}

// =======================================================================
extern "C" void kernel_launch(void* const* d_in, const int* in_sizes, int n_in,
                              void* d_out, int out_size){
    (void)in_sizes; (void)n_in; (void)out_size;
    const float* patch = (const float*)d_in[0];
    const float* noun  = (const float*)d_in[1];
    const float* img   = (const float*)d_in[2];
    const float* txt   = (const float*)d_in[3];
    const float* lsc   = (const float*)d_in[4];
    const int*   idx   = (const int*)d_in[5];
    float* out = (float*)d_out;

    dim3 gsim(9, 64);
    k_sim<<<gsim, 256>>>(patch, noun);
    k_scores<<<64, 256>>>(img, txt);
    k_fine<<<64, 512>>>();
    k_final<<<1, 256>>>(lsc, idx, out);
}

// round 2
// speedup vs baseline: 1.1155x; 1.1155x over previous
#include <cuda_runtime.h>

#define BB 64
#define NP 576
#define DD 512
#define MM 16

__device__ float  g_scaled[BB*MM*NP];   // sim / T
__device__ float  g_scores[BB*BB];
__device__ double g_accs[2];            // [0]=contrast sum, [1]=mask sum

// ---------------- packed f32x2 helpers ----------------
__device__ __forceinline__ void fma2(unsigned long long &acc, unsigned long long a, unsigned long long b){
    asm("fma.rn.f32x2 %0, %1, %2, %0;" : "+l"(acc) : "l"(a), "l"(b));
}
__device__ __forceinline__ float unpack_sum(unsigned long long a){
    float lo, hi;
    asm("mov.b64 {%0,%1}, %2;" : "=f"(lo), "=f"(hi) : "l"(a));
    return lo + hi;
}

// ---------------- top-5 helpers ----------------
__device__ __forceinline__ void top5_insert(float t[5], float a){
    #pragma unroll
    for (int q = 0; q < 5; ++q){
        float mx = fmaxf(t[q], a);
        a        = fminf(t[q], a);
        t[q] = mx;
    }
}
__device__ __forceinline__ float warp_top5_sum(float t[5], int lane, float* write5){
    float total = 0.0f;
    #pragma unroll
    for (int it = 0; it < 5; ++it){
        float v = t[0]; int who = lane;
        #pragma unroll
        for (int d = 16; d >= 1; d >>= 1){
            float ov = __shfl_xor_sync(0xffffffffu, v,   d);
            int   ow = __shfl_xor_sync(0xffffffffu, who, d);
            if (ov > v || (ov == v && ow < who)){ v = ov; who = ow; }
        }
        total += v;
        if (write5 && lane == 0) write5[it] = v;
        if (lane == who){ t[0]=t[1]; t[1]=t[2]; t[2]=t[3]; t[3]=t[4]; t[4]=-1e30f; }
    }
    return total;
}

__device__ __forceinline__ float dot4(float4 a, float4 b){
    return a.x*b.x + a.y*b.y + a.z*b.z + a.w*b.w;
}

// =======================================================================
// Kernel 1: sim[b,m,n]/T  (grid (10,64), 256 threads)
//   blockIdx.x in [0,9): sim tiles (P=4 register blocking)
//   blockIdx.x == 9:     global scores row b (merged old k_scores)
// =======================================================================
__global__ __launch_bounds__(256, 1)
void k_sim(const float* __restrict__ patch, const float* __restrict__ noun,
           const float* __restrict__ img,   const float* __restrict__ txt){
    const int b    = blockIdx.y;
    const int lane = threadIdx.x & 31;
    const int warp = threadIdx.x >> 5;

    if (blockIdx.x == 9){
        // ---- scores: row b of img @ txt^T ----
        const float4* ip = reinterpret_cast<const float4*>(img + (size_t)b * DD);
        float4 a0 = ip[lane], a1 = ip[lane+32], a2 = ip[lane+64], a3 = ip[lane+96];
        for (int tj = 0; tj < 8; ++tj){
            int j = warp * 8 + tj;
            const float4* tp = reinterpret_cast<const float4*>(txt + (size_t)j * DD);
            float s = dot4(a0, tp[lane]) + dot4(a1, tp[lane+32])
                    + dot4(a2, tp[lane+64]) + dot4(a3, tp[lane+96]);
            #pragma unroll
            for (int d = 16; d >= 1; d >>= 1) s += __shfl_xor_sync(0xffffffffu, s, d);
            if (lane == 0) g_scores[b * BB + j] = s;
        }
        return;
    }

    __shared__ ulonglong2 noun_s[MM * DD / 4];   // 32 KB, [m][f4idx]

    if (blockIdx.x == 0 && blockIdx.y == 0 && threadIdx.x == 0){
        g_accs[0] = 0.0; g_accs[1] = 0.0;
    }

    const ulonglong2* np = reinterpret_cast<const ulonglong2*>(noun + (size_t)b * MM * DD);
    for (int i = threadIdx.x; i < MM * DD / 4; i += 256) noun_s[i] = np[i];
    __syncthreads();

    const float INVT = (float)(1.0 / 0.07);

    for (int g = 0; g < 2; ++g){
        const int n0 = blockIdx.x * 64 + warp * 8 + g * 4;
        unsigned long long acc[4][16];
        #pragma unroll
        for (int p = 0; p < 4; ++p)
            #pragma unroll
            for (int m = 0; m < 16; ++m) acc[p][m] = 0ull;

        const ulonglong2* pb =
            reinterpret_cast<const ulonglong2*>(patch) + ((size_t)b * NP + n0) * (DD / 4);

        #pragma unroll
        for (int j = 0; j < 4; ++j){
            ulonglong2 pf[4];
            #pragma unroll
            for (int p = 0; p < 4; ++p) pf[p] = pb[p * (DD/4) + lane + 32 * j];
            #pragma unroll
            for (int m = 0; m < 16; ++m){
                ulonglong2 nf = noun_s[m * (DD/4) + lane + 32 * j];
                #pragma unroll
                for (int p = 0; p < 4; ++p){
                    fma2(acc[p][m], pf[p].x, nf.x);
                    fma2(acc[p][m], pf[p].y, nf.y);
                }
            }
        }

        // 64 per-lane partials -> 64 warp sums, multi-value butterfly (62 shfl)
        float v[64];
        #pragma unroll
        for (int p = 0; p < 4; ++p)
            #pragma unroll
            for (int m = 0; m < 16; ++m) v[p*16 + m] = unpack_sum(acc[p][m]);

        float w32[32];
        #pragma unroll
        for (int i = 0; i < 32; ++i){
            float send = (lane & 16) ? v[i] : v[i+32];
            float recv = __shfl_xor_sync(0xffffffffu, send, 16);
            w32[i] = ((lane & 16) ? v[i+32] : v[i]) + recv;
        }
        float w16[16];
        #pragma unroll
        for (int i = 0; i < 16; ++i){
            float send = (lane & 8) ? w32[i] : w32[i+16];
            float recv = __shfl_xor_sync(0xffffffffu, send, 8);
            w16[i] = ((lane & 8) ? w32[i+16] : w32[i]) + recv;
        }
        float w8[8];
        #pragma unroll
        for (int i = 0; i < 8; ++i){
            float send = (lane & 4) ? w16[i] : w16[i+8];
            float recv = __shfl_xor_sync(0xffffffffu, send, 4);
            w8[i] = ((lane & 4) ? w16[i+8] : w16[i]) + recv;
        }
        float w4[4];
        #pragma unroll
        for (int i = 0; i < 4; ++i){
            float send = (lane & 2) ? w8[i] : w8[i+4];
            float recv = __shfl_xor_sync(0xffffffffu, send, 2);
            w4[i] = ((lane & 2) ? w8[i+4] : w8[i]) + recv;
        }
        float w2[2];
        #pragma unroll
        for (int i = 0; i < 2; ++i){
            float send = (lane & 1) ? w4[i] : w4[i+2];
            float recv = __shfl_xor_sync(0xffffffffu, send, 1);
            w2[i] = ((lane & 1) ? w4[i+2] : w4[i]) + recv;
        }
        #pragma unroll
        for (int j2 = 0; j2 < 2; ++j2){
            int o = 2 * lane + j2;
            int p = o >> 4, m = o & 15;
            g_scaled[((size_t)b * MM + m) * NP + n0 + p] = w2[j2] * INVT;
        }
    }
}

// =======================================================================
// Kernel 2: fine-grained reductions (grid 64, 512 threads = 16 warps)
// =======================================================================
__global__ __launch_bounds__(512)
void k_fine(){
    const int b    = blockIdx.x;
    const int lane = threadIdx.x & 31;
    const int w    = threadIdx.x >> 5;

    __shared__ float s_sp[16];
    __shared__ float s_top[16 * 5];

    // ---- part A: per-noun (m = w) lse + top5 ----
    const float* row = g_scaled + ((size_t)b * MM + w) * NP;
    float t[5] = {-1e30f, -1e30f, -1e30f, -1e30f, -1e30f};
    for (int i = lane; i < NP; i += 32) top5_insert(t, row[i]);

    float MX = t[0];
    #pragma unroll
    for (int d = 16; d >= 1; d >>= 1) MX = fmaxf(MX, __shfl_xor_sync(0xffffffffu, MX, d));

    float se = 0.0f;
    for (int i = lane; i < NP; i += 32) se += __expf(row[i] - MX);
    #pragma unroll
    for (int d = 16; d >= 1; d >>= 1) se += __shfl_xor_sync(0xffffffffu, se, d);

    float tsum = warp_top5_sum(t, lane, nullptr);
    if (lane == 0){
        float lse = MX + __logf(se);
        atomicAdd(&g_accs[0], (double)(5.0f * lse - tsum));
    }

    // ---- part B: pooled x, softplus sum, block top-5 ----
    float u[5] = {-1e30f, -1e30f, -1e30f, -1e30f, -1e30f};
    float sp = 0.0f;
    const float* base = g_scaled + (size_t)b * MM * NP;
    #pragma unroll
    for (int rep = 0; rep < 2; ++rep){
        int n = threadIdx.x + rep * 512;
        if (n < NP){
            float s = 0.0f;
            #pragma unroll
            for (int m = 0; m < 16; ++m) s += base[m * NP + n];
            float x = s * (1.0f / 16.0f);
            sp += fmaxf(x, 0.0f) + __logf(1.0f + __expf(-fabsf(x)));
            top5_insert(u, x);
        }
    }
    #pragma unroll
    for (int d = 16; d >= 1; d >>= 1) sp += __shfl_xor_sync(0xffffffffu, sp, d);
    if (lane == 0) s_sp[w] = sp;

    warp_top5_sum(u, lane, &s_top[w * 5]);
    __syncthreads();

    if (w == 0){
        float q[5] = {-1e30f, -1e30f, -1e30f, -1e30f, -1e30f};
        for (int i = lane; i < 80; i += 32) top5_insert(q, s_top[i]);
        float fsum = warp_top5_sum(q, lane, nullptr);

        float tot = (lane < 16) ? s_sp[lane] : 0.0f;
        #pragma unroll
        for (int d = 16; d >= 1; d >>= 1) tot += __shfl_xor_sync(0xffffffffu, tot, d);

        if (lane == 0) atomicAdd(&g_accs[1], (double)(tot - fsum));
    }
}

// =======================================================================
// Kernel 3: contrastive + triplet + final combine (1 block, 1024 threads)
// Warp w handles rows/cols {2w, 2w+1}; lane covers j = lane, lane+32.
// =======================================================================
__global__ __launch_bounds__(1024)
void k_final(const float* __restrict__ logit_scale, const int* __restrict__ idx,
             float* __restrict__ out){
    __shared__ float sc[64][65];
    __shared__ int   sidx[64];
    __shared__ float redc[32];
    __shared__ float redt[32];
    const int tid  = threadIdx.x;
    const int lane = tid & 31;
    const int w    = tid >> 5;

    #pragma unroll
    for (int e = tid; e < 4096; e += 1024) sc[e >> 6][e & 63] = g_scores[e];
    if (tid < 64) sidx[tid] = idx[tid];
    __syncthreads();

    const float s = logit_scale[0];

    float contrib = 0.0f;
    #pragma unroll
    for (int rr = 0; rr < 2; ++rr){
        const int r = w * 2 + rr;
        const int myid = sidx[r];
        const int m0 = (sidx[lane]      == myid);
        const int m1 = (sidx[lane + 32] == myid);

        // ---- row r of logits: li2t ----
        float a0 = s * sc[r][lane], a1 = s * sc[r][lane + 32];
        float mx = fmaxf(a0, a1);
        #pragma unroll
        for (int d = 16; d >= 1; d >>= 1) mx = fmaxf(mx, __shfl_xor_sync(0xffffffffu, mx, d));
        float se   = __expf(a0 - mx) + __expf(a1 - mx);
        float ms   = (m0 ? a0 : 0.0f) + (m1 ? a1 : 0.0f);
        float cntf = (float)(m0 + m1);
        #pragma unroll
        for (int d = 16; d >= 1; d >>= 1){
            se   += __shfl_xor_sync(0xffffffffu, se,   d);
            ms   += __shfl_xor_sync(0xffffffffu, ms,   d);
            cntf += __shfl_xor_sync(0xffffffffu, cntf, d);
        }
        float li2t = mx + __logf(se) - ms / cntf;

        // ---- column r of logits: lt2i ----
        float b0 = s * sc[lane][r], b1 = s * sc[lane + 32][r];
        float mxc = fmaxf(b0, b1);
        #pragma unroll
        for (int d = 16; d >= 1; d >>= 1) mxc = fmaxf(mxc, __shfl_xor_sync(0xffffffffu, mxc, d));
        float sec = __expf(b0 - mxc) + __expf(b1 - mxc);
        float ms2 = (m0 ? b0 : 0.0f) + (m1 ? b1 : 0.0f);
        #pragma unroll
        for (int d = 16; d >= 1; d >>= 1){
            sec += __shfl_xor_sync(0xffffffffu, sec, d);
            ms2 += __shfl_xor_sync(0xffffffffu, ms2, d);
        }
        float lt2i = mxc + __logf(sec) - ms2 / cntf;

        contrib += 0.5f * (li2t + lt2i);
    }
    if (lane == 0) redc[w] = contrib;   // warp-uniform after xor reductions

    // ---- triplet (4 elements per thread) ----
    float mt = 0.0f;
    #pragma unroll
    for (int e = tid; e < 4096; e += 1024){
        int i = e >> 6, j = e & 63;
        if (i != j){
            float v = sc[i][j];
            mt += fmaxf(0.0f, 0.1f + v - sc[i][i]) + fmaxf(0.0f, 0.1f + v - sc[j][j]);
        }
    }
    #pragma unroll
    for (int d = 16; d >= 1; d >>= 1) mt += __shfl_xor_sync(0xffffffffu, mt, d);
    if (lane == 0) redt[w] = mt;
    __syncthreads();

    if (w == 0){
        float c = redc[lane];
        float t = redt[lane];
        #pragma unroll
        for (int d = 16; d >= 1; d >>= 1){
            c += __shfl_xor_sync(0xffffffffu, c, d);
            t += __shfl_xor_sync(0xffffffffu, t, d);
        }
        if (lane == 0){
            out[0] = c / 64.0f;
            out[1] = 0.5f * t;
            double contrast = g_accs[0] / (double)(BB * MM);
            double mask     = g_accs[1] / (double)(BB * NP);
            out[2] = (float)(0.6 * contrast + 0.4 * mask);
        }
    }
}

// =======================================================================
extern "C" void kernel_launch(void* const* d_in, const int* in_sizes, int n_in,
                              void* d_out, int out_size){
    (void)in_sizes; (void)n_in; (void)out_size;
    const float* patch = (const float*)d_in[0];
    const float* noun  = (const float*)d_in[1];
    const float* img   = (const float*)d_in[2];
    const float* txt   = (const float*)d_in[3];
    const float* lsc   = (const float*)d_in[4];
    const int*   idx   = (const int*)d_in[5];
    float* out = (float*)d_out;

    dim3 gsim(10, 64);
    k_sim<<<gsim, 256>>>(patch, noun, img, txt);
    k_fine<<<64, 512>>>();
    k_final<<<1, 1024>>>(lsc, idx, out);
}

// round 3
// speedup vs baseline: 3.3158x; 2.9726x over previous
#include <cuda_runtime.h>

#define BB 64
#define NP 576
#define DD 512
#define MM 16
#define NCHUNK 36            // 16-patch chunks per batch = 6 blocks x 6 warps

__device__ float  g_scores[BB*BB];
__device__ float  g_pooled[BB*NP];
__device__ float  g_mx [BB*MM*NCHUNK];
__device__ float  g_se [BB*MM*NCHUNK];
__device__ float  g_t5 [BB*MM*NCHUNK*5];
__device__ double g_accs[2];        // [0]=contrast sum, [1]=mask sum

// ---------------- helpers ----------------
__device__ __forceinline__ float dot4(float4 a, float4 b){
    return a.x*b.x + a.y*b.y + a.z*b.z + a.w*b.w;
}
__device__ __forceinline__ void top5_insert(float t[5], float a){
    #pragma unroll
    for (int q = 0; q < 5; ++q){
        float mx = fmaxf(t[q], a);
        a        = fminf(t[q], a);
        t[q] = mx;
    }
}
__device__ __forceinline__ float warp_top5_sum(float t[5], int lane, float* write5){
    float total = 0.0f;
    #pragma unroll
    for (int it = 0; it < 5; ++it){
        float v = t[0]; int who = lane;
        #pragma unroll
        for (int d = 16; d >= 1; d >>= 1){
            float ov = __shfl_xor_sync(0xffffffffu, v,   d);
            int   ow = __shfl_xor_sync(0xffffffffu, who, d);
            if (ov > v || (ov == v && ow < who)){ v = ov; who = ow; }
        }
        total += v;
        if (write5 && lane == 0) write5[it] = v;
        if (lane == who){ t[0]=t[1]; t[1]=t[2]; t[2]=t[3]; t[3]=t[4]; t[4]=-1e30f; }
    }
    return total;
}
// tf32 MMA: D(16x8,f32) += A(16x8) * B(8x8). fp32 bits passed as tf32 (HW truncates).
__device__ __forceinline__ void mma_tf32(float c[4], float a0, float a1, float a2, float a3,
                                         float b0, float b1){
    asm volatile(
        "mma.sync.aligned.m16n8k8.row.col.f32.tf32.tf32.f32 "
        "{%0,%1,%2,%3}, {%4,%5,%6,%7}, {%8,%9}, {%0,%1,%2,%3};"
        : "+f"(c[0]), "+f"(c[1]), "+f"(c[2]), "+f"(c[3])
        : "r"(__float_as_uint(a0)), "r"(__float_as_uint(a1)),
          "r"(__float_as_uint(a2)), "r"(__float_as_uint(a3)),
          "r"(__float_as_uint(b0)), "r"(__float_as_uint(b1)));
}

// =======================================================================
// Kernel 1: per-batch GEMM tiles + in-register stats.  grid (7,64), 192 thr.
//   bx in [0,6): 96 patches x 16 nouns via tf32 MMA, emit chunk stats
//   bx == 6   : row b of global scores (img @ txt^T); also zero g_accs
// =======================================================================
__global__ __launch_bounds__(192, 2)
void k_sim(const float* __restrict__ patch, const float* __restrict__ noun,
           const float* __restrict__ img,   const float* __restrict__ txt){
    const int b    = blockIdx.y;
    const int lane = threadIdx.x & 31;
    const int w    = threadIdx.x >> 5;       // 0..5

    if (blockIdx.x == 6){
        if (b == 0 && threadIdx.x == 0){ g_accs[0] = 0.0; g_accs[1] = 0.0; }
        const float4* ip = reinterpret_cast<const float4*>(img + (size_t)b * DD);
        float4 a0 = ip[lane], a1 = ip[lane+32], a2 = ip[lane+64], a3 = ip[lane+96];
        for (int j = w; j < BB; j += 6){
            const float4* tp = reinterpret_cast<const float4*>(txt + (size_t)j * DD);
            float s = dot4(a0, tp[lane]) + dot4(a1, tp[lane+32])
                    + dot4(a2, tp[lane+64]) + dot4(a3, tp[lane+96]);
            #pragma unroll
            for (int d = 16; d >= 1; d >>= 1) s += __shfl_xor_sync(0xffffffffu, s, d);
            if (lane == 0) g_scores[b * BB + j] = s;
        }
        return;
    }

    const int q   = lane & 3;       // col-group / k-selector
    const int gid = lane >> 2;      // row-group / noun-selector
    const int rowbase = blockIdx.x * 96 + w * 16;
    const int row0 = rowbase + gid;

    // A: patch rows row0 and row0+8; B: noun rows gid and gid+8 (k-major both)
    const float4* Alo = reinterpret_cast<const float4*>(patch + ((size_t)b*NP + row0) * DD);
    const float4* Ahi = Alo + 8 * (DD/4);
    const float4* B0  = reinterpret_cast<const float4*>(noun  + ((size_t)b*MM + gid) * DD);
    const float4* B1  = B0 + 8 * (DD/4);

    float cH0[4] = {0,0,0,0};   // nouns 0..7
    float cH1[4] = {0,0,0,0};   // nouns 8..15

    // K permutation inside each 16-col window: thread q owns cols 16p+4q..+3,
    // applied identically to A and B fragments -> contiguous float4 loads.
    #pragma unroll 4
    for (int p = 0; p < 32; ++p){
        const int o = 4*p + q;
        float4 alo = Alo[o];
        float4 ahi = Ahi[o];
        float4 b0  = B0[o];
        float4 b1  = B1[o];
        mma_tf32(cH0, alo.x, ahi.x, alo.y, ahi.y, b0.x, b0.y);
        mma_tf32(cH1, alo.x, ahi.x, alo.y, ahi.y, b1.x, b1.y);
        mma_tf32(cH0, alo.z, ahi.z, alo.w, ahi.w, b0.z, b0.w);
        mma_tf32(cH1, alo.z, ahi.z, alo.w, ahi.w, b1.z, b1.w);
    }

    // scale to sim/T space
    const float INVT = (float)(1.0 / 0.07);
    #pragma unroll
    for (int i = 0; i < 4; ++i){ cH0[i] *= INVT; cH1[i] *= INVT; }

    // C layout: lane holds rows {gid, gid+8}, cols {2q,2q+1} (+8 for cH1):
    //   c[0]=C[gid][2q]  c[1]=C[gid][2q+1]  c[2]=C[gid+8][2q]  c[3]=C[gid+8][2q+1]
    const int chunk = blockIdx.x * 6 + w;

    // ---- per-noun column stats over the warp's 16 patches ----
    // unit u: (col, v0=row gid, v1=row gid+8)
    #pragma unroll
    for (int u = 0; u < 4; ++u){
        float v0, v1; int col;
        if      (u == 0){ col = 2*q;     v0 = cH0[0]; v1 = cH0[2]; }
        else if (u == 1){ col = 2*q + 1; v0 = cH0[1]; v1 = cH0[3]; }
        else if (u == 2){ col = 2*q + 8; v0 = cH1[0]; v1 = cH1[2]; }
        else            { col = 2*q + 9; v0 = cH1[1]; v1 = cH1[3]; }

        // max over 16 rows (xor 4/8/16 mixes only same-q lanes)
        float mx = fmaxf(v0, v1);
        #pragma unroll
        for (int d = 4; d <= 16; d <<= 1) mx = fmaxf(mx, __shfl_xor_sync(0xffffffffu, mx, d));
        // sum exp
        float se = __expf(v0 - mx) + __expf(v1 - mx);
        #pragma unroll
        for (int d = 4; d <= 16; d <<= 1) se += __shfl_xor_sync(0xffffffffu, se, d);
        // top5 over 16 rows
        float t[5] = {fmaxf(v0,v1), fminf(v0,v1), -1e30f, -1e30f, -1e30f};
        #pragma unroll
        for (int d = 4; d <= 16; d <<= 1){
            float o0 = __shfl_xor_sync(0xffffffffu, t[0], d);
            float o1 = __shfl_xor_sync(0xffffffffu, t[1], d);
            float o2 = __shfl_xor_sync(0xffffffffu, t[2], d);
            float o3 = __shfl_xor_sync(0xffffffffu, t[3], d);
            float o4 = __shfl_xor_sync(0xffffffffu, t[4], d);
            top5_insert(t, o0); top5_insert(t, o1); top5_insert(t, o2);
            top5_insert(t, o3); top5_insert(t, o4);
        }
        if (gid == 0){
            int base = (b * MM + col) * NCHUNK + chunk;
            g_mx[base] = mx;
            g_se[base] = se;
            #pragma unroll
            for (int i = 0; i < 5; ++i) g_t5[base*5 + i] = t[i];
        }
    }

    // ---- pooled (row sums over all 16 nouns), in scaled space ----
    float r0 = cH0[0] + cH0[1] + cH1[0] + cH1[1];
    float r1 = cH0[2] + cH0[3] + cH1[2] + cH1[3];
    r0 += __shfl_xor_sync(0xffffffffu, r0, 1);
    r0 += __shfl_xor_sync(0xffffffffu, r0, 2);
    r1 += __shfl_xor_sync(0xffffffffu, r1, 1);
    r1 += __shfl_xor_sync(0xffffffffu, r1, 2);
    if (q == 0){
        g_pooled[b * NP + rowbase + gid]     = r0 * (1.0f/16.0f);
        g_pooled[b * NP + rowbase + gid + 8] = r1 * (1.0f/16.0f);
    }
}

// =======================================================================
// Kernel 2: merge chunk stats. grid 64 (one per batch), 256 threads.
// =======================================================================
__global__ __launch_bounds__(256)
void k_fine(){
    const int b    = blockIdx.x;
    const int lane = threadIdx.x & 31;
    const int w    = threadIdx.x >> 5;     // 0..7

    __shared__ float s_red[8];
    __shared__ float s_sp[8];
    __shared__ float s_top[8 * 5];

    // ---- part A: per-noun lse + top5 merged over 36 chunks ----
    float contrib = 0.0f;
    #pragma unroll
    for (int mi = 0; mi < 2; ++mi){
        const int m = w + mi * 8;
        const int base = (b * MM + m) * NCHUNK;
        float mxA = g_mx[base + lane];
        float mxB = (lane < 4) ? g_mx[base + 32 + lane] : -1e30f;
        float mx = fmaxf(mxA, mxB);
        #pragma unroll
        for (int d = 16; d >= 1; d >>= 1) mx = fmaxf(mx, __shfl_xor_sync(0xffffffffu, mx, d));
        float se = g_se[base + lane] * __expf(mxA - mx);
        if (lane < 4) se += g_se[base + 32 + lane] * __expf(mxB - mx);
        #pragma unroll
        for (int d = 16; d >= 1; d >>= 1) se += __shfl_xor_sync(0xffffffffu, se, d);

        float t[5] = {-1e30f, -1e30f, -1e30f, -1e30f, -1e30f};
        #pragma unroll
        for (int i = 0; i < 5; ++i) top5_insert(t, g_t5[(base + lane)*5 + i]);
        if (lane < 4){
            #pragma unroll
            for (int i = 0; i < 5; ++i) top5_insert(t, g_t5[(base + 32 + lane)*5 + i]);
        }
        float tsum = warp_top5_sum(t, lane, nullptr);
        float lse = mx + __logf(se);
        contrib += 5.0f * lse - tsum;
    }
    if (lane == 0) s_red[w] = contrib;

    // ---- part B: pooled softplus sum + top5 over 576 ----
    float u[5] = {-1e30f, -1e30f, -1e30f, -1e30f, -1e30f};
    float sp = 0.0f;
    for (int n = threadIdx.x; n < NP; n += 256){
        float x = g_pooled[b * NP + n];
        sp += fmaxf(x, 0.0f) + __logf(1.0f + __expf(-fabsf(x)));
        top5_insert(u, x);
    }
    #pragma unroll
    for (int d = 16; d >= 1; d >>= 1) sp += __shfl_xor_sync(0xffffffffu, sp, d);
    if (lane == 0) s_sp[w] = sp;
    warp_top5_sum(u, lane, &s_top[w * 5]);
    __syncthreads();

    if (w == 0){
        float qq[5] = {-1e30f, -1e30f, -1e30f, -1e30f, -1e30f};
        if (lane < 40) top5_insert(qq, s_top[lane]);
        if (lane < 8)  top5_insert(qq, s_top[lane + 32]);
        float ftop = warp_top5_sum(qq, lane, nullptr);

        float spt = (lane < 8) ? s_sp[lane] : 0.0f;
        float crt = (lane < 8) ? s_red[lane] : 0.0f;
        #pragma unroll
        for (int d = 16; d >= 1; d >>= 1){
            spt += __shfl_xor_sync(0xffffffffu, spt, d);
            crt += __shfl_xor_sync(0xffffffffu, crt, d);
        }
        if (lane == 0){
            atomicAdd(&g_accs[0], (double)crt);
            atomicAdd(&g_accs[1], (double)(spt - ftop));
        }
    }
}

// =======================================================================
// Kernel 3: contrastive + triplet + combine (1 block, 1024 threads)
// =======================================================================
__global__ __launch_bounds__(1024)
void k_final(const float* __restrict__ logit_scale, const int* __restrict__ idx,
             float* __restrict__ out){
    __shared__ float sc[64][65];
    __shared__ int   sidx[64];
    __shared__ float redc[32];
    __shared__ float redt[32];
    const int tid  = threadIdx.x;
    const int lane = tid & 31;
    const int w    = tid >> 5;

    #pragma unroll
    for (int e = tid; e < 4096; e += 1024) sc[e >> 6][e & 63] = g_scores[e];
    if (tid < 64) sidx[tid] = idx[tid];
    __syncthreads();

    const float s = logit_scale[0];

    float contrib = 0.0f;
    #pragma unroll
    for (int rr = 0; rr < 2; ++rr){
        const int r = w * 2 + rr;
        const int myid = sidx[r];
        const int m0 = (sidx[lane]      == myid);
        const int m1 = (sidx[lane + 32] == myid);

        float a0 = s * sc[r][lane], a1 = s * sc[r][lane + 32];
        float mx = fmaxf(a0, a1);
        #pragma unroll
        for (int d = 16; d >= 1; d >>= 1) mx = fmaxf(mx, __shfl_xor_sync(0xffffffffu, mx, d));
        float se   = __expf(a0 - mx) + __expf(a1 - mx);
        float ms   = (m0 ? a0 : 0.0f) + (m1 ? a1 : 0.0f);
        float cntf = (float)(m0 + m1);
        #pragma unroll
        for (int d = 16; d >= 1; d >>= 1){
            se   += __shfl_xor_sync(0xffffffffu, se,   d);
            ms   += __shfl_xor_sync(0xffffffffu, ms,   d);
            cntf += __shfl_xor_sync(0xffffffffu, cntf, d);
        }
        float li2t = mx + __logf(se) - ms / cntf;

        float b0 = s * sc[lane][r], b1 = s * sc[lane + 32][r];
        float mxc = fmaxf(b0, b1);
        #pragma unroll
        for (int d = 16; d >= 1; d >>= 1) mxc = fmaxf(mxc, __shfl_xor_sync(0xffffffffu, mxc, d));
        float sec = __expf(b0 - mxc) + __expf(b1 - mxc);
        float ms2 = (m0 ? b0 : 0.0f) + (m1 ? b1 : 0.0f);
        #pragma unroll
        for (int d = 16; d >= 1; d >>= 1){
            sec += __shfl_xor_sync(0xffffffffu, sec, d);
            ms2 += __shfl_xor_sync(0xffffffffu, ms2, d);
        }
        float lt2i = mxc + __logf(sec) - ms2 / cntf;

        contrib += 0.5f * (li2t + lt2i);
    }
    if (lane == 0) redc[w] = contrib;

    float mt = 0.0f;
    #pragma unroll
    for (int e = tid; e < 4096; e += 1024){
        int i = e >> 6, j = e & 63;
        if (i != j){
            float v = sc[i][j];
            mt += fmaxf(0.0f, 0.1f + v - sc[i][i]) + fmaxf(0.0f, 0.1f + v - sc[j][j]);
        }
    }
    #pragma unroll
    for (int d = 16; d >= 1; d >>= 1) mt += __shfl_xor_sync(0xffffffffu, mt, d);
    if (lane == 0) redt[w] = mt;
    __syncthreads();

    if (w == 0){
        float c = redc[lane];
        float t = redt[lane];
        #pragma unroll
        for (int d = 16; d >= 1; d >>= 1){
            c += __shfl_xor_sync(0xffffffffu, c, d);
            t += __shfl_xor_sync(0xffffffffu, t, d);
        }
        if (lane == 0){
            out[0] = c / 64.0f;
            out[1] = 0.5f * t;
            double contrast = g_accs[0] / (double)(BB * MM);
            double mask     = g_accs[1] / (double)(BB * NP);
            out[2] = (float)(0.6 * contrast + 0.4 * mask);
        }
    }
}

// =======================================================================
extern "C" void kernel_launch(void* const* d_in, const int* in_sizes, int n_in,
                              void* d_out, int out_size){
    (void)in_sizes; (void)n_in; (void)out_size;
    const float* patch = (const float*)d_in[0];
    const float* noun  = (const float*)d_in[1];
    const float* img   = (const float*)d_in[2];
    const float* txt   = (const float*)d_in[3];
    const float* lsc   = (const float*)d_in[4];
    const int*   idx   = (const int*)d_in[5];
    float* out = (float*)d_out;

    dim3 gsim(7, 64);
    k_sim<<<gsim, 192>>>(patch, noun, img, txt);
    k_fine<<<64, 256>>>();
    k_final<<<1, 1024>>>(lsc, idx, out);
}

// round 4
// speedup vs baseline: 3.5327x; 1.0654x over previous
#include <cuda_runtime.h>

#define BB 64
#define NP 576
#define DD 512
#define MM 16
#define NCHUNK 18            // 32-patch chunks per batch = 3 blocks x 6 warps

__device__ float    g_scores[BB*BB];
__device__ float    g_pooled[BB*NP];
__device__ float    g_mx [BB*MM*NCHUNK];
__device__ float    g_se [BB*MM*NCHUNK];
__device__ float    g_t5 [BB*MM*NCHUNK*5];
__device__ double   g_accs[2];        // [0]=contrast sum, [1]=mask sum
__device__ unsigned g_cnt;

// ---------------- helpers ----------------
__device__ __forceinline__ float dot4(float4 a, float4 b){
    return a.x*b.x + a.y*b.y + a.z*b.z + a.w*b.w;
}
__device__ __forceinline__ void top5_insert(float t[5], float a){
    #pragma unroll
    for (int q = 0; q < 5; ++q){
        float mx = fmaxf(t[q], a);
        a        = fminf(t[q], a);
        t[q] = mx;
    }
}
__device__ __forceinline__ float warp_top5_sum(float t[5], int lane, float* write5){
    float total = 0.0f;
    #pragma unroll
    for (int it = 0; it < 5; ++it){
        float v = t[0]; int who = lane;
        #pragma unroll
        for (int d = 16; d >= 1; d >>= 1){
            float ov = __shfl_xor_sync(0xffffffffu, v,   d);
            int   ow = __shfl_xor_sync(0xffffffffu, who, d);
            if (ov > v || (ov == v && ow < who)){ v = ov; who = ow; }
        }
        total += v;
        if (write5 && lane == 0) write5[it] = v;
        if (lane == who){ t[0]=t[1]; t[1]=t[2]; t[2]=t[3]; t[3]=t[4]; t[4]=-1e30f; }
    }
    return total;
}
// tf32 MMA: D(16x8,f32) += A(16x8) * B(8x8). fp32 bits passed as tf32 (HW truncates).
__device__ __forceinline__ void mma_tf32(float c[4], float a0, float a1, float a2, float a3,
                                         float b0, float b1){
    asm volatile(
        "mma.sync.aligned.m16n8k8.row.col.f32.tf32.tf32.f32 "
        "{%0,%1,%2,%3}, {%4,%5,%6,%7}, {%8,%9}, {%0,%1,%2,%3};"
        : "+f"(c[0]), "+f"(c[1]), "+f"(c[2]), "+f"(c[3])
        : "r"(__float_as_uint(a0)), "r"(__float_as_uint(a1)),
          "r"(__float_as_uint(a2)), "r"(__float_as_uint(a3)),
          "r"(__float_as_uint(b0)), "r"(__float_as_uint(b1)));
}

// =======================================================================
// Kernel 1: per-batch GEMM tiles + in-register stats.  grid (4,64), 192 thr.
//   bx in [0,3): 192 patches x 16 nouns via tf32 MMA (32 patches/warp)
//   bx == 3   : row b of global scores; b==0 also zeroes accumulators
// =======================================================================
__global__ __launch_bounds__(192, 3)
void k_sim(const float* __restrict__ patch, const float* __restrict__ noun,
           const float* __restrict__ img,   const float* __restrict__ txt){
    const int b    = blockIdx.y;
    const int lane = threadIdx.x & 31;
    const int w    = threadIdx.x >> 5;       // 0..5

    if (blockIdx.x == 3){
        if (b == 0 && threadIdx.x == 0){ g_accs[0] = 0.0; g_accs[1] = 0.0; g_cnt = 0u; }
        const float4* ip = reinterpret_cast<const float4*>(img + (size_t)b * DD);
        float4 a0 = ip[lane], a1 = ip[lane+32], a2 = ip[lane+64], a3 = ip[lane+96];
        for (int j = w; j < BB; j += 6){
            const float4* tp = reinterpret_cast<const float4*>(txt + (size_t)j * DD);
            float s = dot4(a0, tp[lane]) + dot4(a1, tp[lane+32])
                    + dot4(a2, tp[lane+64]) + dot4(a3, tp[lane+96]);
            #pragma unroll
            for (int d = 16; d >= 1; d >>= 1) s += __shfl_xor_sync(0xffffffffu, s, d);
            if (lane == 0) g_scores[b * BB + j] = s;
        }
        return;
    }

    const int q   = lane & 3;       // col-group / k-selector
    const int gid = lane >> 2;      // row-group / noun-selector
    const int rowbase = blockIdx.x * 192 + w * 32;

    // Tile0 rows: rowbase+gid, +8 ; Tile1 rows: rowbase+16+gid, +24
    const float4* A0 = reinterpret_cast<const float4*>(patch + ((size_t)b*NP + rowbase + gid) * DD);
    const float4* A1 = A0 + 8  * (DD/4);
    const float4* A2 = A0 + 16 * (DD/4);
    const float4* A3 = A0 + 24 * (DD/4);
    const float4* B0 = reinterpret_cast<const float4*>(noun + ((size_t)b*MM + gid) * DD);
    const float4* B1 = B0 + 8 * (DD/4);

    float c00[4] = {0,0,0,0};   // tile0, nouns 0..7
    float c01[4] = {0,0,0,0};   // tile0, nouns 8..15
    float c10[4] = {0,0,0,0};   // tile1, nouns 0..7
    float c11[4] = {0,0,0,0};   // tile1, nouns 8..15

    // K permutation inside each 16-col window: thread q owns cols 16p+4q..+3,
    // applied identically to A and B fragments -> contiguous float4 loads.
    #pragma unroll 4
    for (int p = 0; p < 32; ++p){
        const int o = 4*p + q;
        float4 a0 = A0[o];
        float4 a1 = A1[o];
        float4 a2 = A2[o];
        float4 a3 = A3[o];
        float4 b0 = B0[o];
        float4 b1 = B1[o];
        mma_tf32(c00, a0.x, a1.x, a0.y, a1.y, b0.x, b0.y);
        mma_tf32(c01, a0.x, a1.x, a0.y, a1.y, b1.x, b1.y);
        mma_tf32(c10, a2.x, a3.x, a2.y, a3.y, b0.x, b0.y);
        mma_tf32(c11, a2.x, a3.x, a2.y, a3.y, b1.x, b1.y);
        mma_tf32(c00, a0.z, a1.z, a0.w, a1.w, b0.z, b0.w);
        mma_tf32(c01, a0.z, a1.z, a0.w, a1.w, b1.z, b1.w);
        mma_tf32(c10, a2.z, a3.z, a2.w, a3.w, b0.z, b0.w);
        mma_tf32(c11, a2.z, a3.z, a2.w, a3.w, b1.z, b1.w);
    }

    const float INVT = (float)(1.0 / 0.07);
    #pragma unroll
    for (int i = 0; i < 4; ++i){
        c00[i] *= INVT; c01[i] *= INVT; c10[i] *= INVT; c11[i] *= INVT;
    }

    // C layout per tile: c[0]=C[gid][2q] c[1]=C[gid][2q+1] c[2]=C[gid+8][2q] c[3]=C[gid+8][2q+1]
    const int chunk = blockIdx.x * 6 + w;

    // ---- per-noun column stats over the warp's 32 patches ----
    #pragma unroll
    for (int u = 0; u < 4; ++u){
        float v0, v1, v2, v3; int col;
        if      (u == 0){ col = 2*q;     v0 = c00[0]; v1 = c00[2]; v2 = c10[0]; v3 = c10[2]; }
        else if (u == 1){ col = 2*q + 1; v0 = c00[1]; v1 = c00[3]; v2 = c10[1]; v3 = c10[3]; }
        else if (u == 2){ col = 2*q + 8; v0 = c01[0]; v1 = c01[2]; v2 = c11[0]; v3 = c11[2]; }
        else            { col = 2*q + 9; v0 = c01[1]; v1 = c01[3]; v2 = c11[1]; v3 = c11[3]; }

        float mx = fmaxf(fmaxf(v0, v1), fmaxf(v2, v3));
        #pragma unroll
        for (int d = 4; d <= 16; d <<= 1) mx = fmaxf(mx, __shfl_xor_sync(0xffffffffu, mx, d));
        float se = __expf(v0 - mx) + __expf(v1 - mx) + __expf(v2 - mx) + __expf(v3 - mx);
        #pragma unroll
        for (int d = 4; d <= 16; d <<= 1) se += __shfl_xor_sync(0xffffffffu, se, d);

        float t[5] = {-1e30f, -1e30f, -1e30f, -1e30f, -1e30f};
        top5_insert(t, v0); top5_insert(t, v1); top5_insert(t, v2); top5_insert(t, v3);
        #pragma unroll
        for (int d = 4; d <= 16; d <<= 1){
            float o0 = __shfl_xor_sync(0xffffffffu, t[0], d);
            float o1 = __shfl_xor_sync(0xffffffffu, t[1], d);
            float o2 = __shfl_xor_sync(0xffffffffu, t[2], d);
            float o3 = __shfl_xor_sync(0xffffffffu, t[3], d);
            float o4 = __shfl_xor_sync(0xffffffffu, t[4], d);
            top5_insert(t, o0); top5_insert(t, o1); top5_insert(t, o2);
            top5_insert(t, o3); top5_insert(t, o4);
        }
        if (gid == 0){
            int base = (b * MM + col) * NCHUNK + chunk;
            g_mx[base] = mx;
            g_se[base] = se;
            #pragma unroll
            for (int i = 0; i < 5; ++i) g_t5[base*5 + i] = t[i];
        }
    }

    // ---- pooled row sums over all 16 nouns (scaled space) ----
    float r0 = c00[0] + c00[1] + c01[0] + c01[1];
    float r1 = c00[2] + c00[3] + c01[2] + c01[3];
    float r2 = c10[0] + c10[1] + c11[0] + c11[1];
    float r3 = c10[2] + c10[3] + c11[2] + c11[3];
    #pragma unroll
    for (int d = 1; d <= 2; d <<= 1){
        r0 += __shfl_xor_sync(0xffffffffu, r0, d);
        r1 += __shfl_xor_sync(0xffffffffu, r1, d);
        r2 += __shfl_xor_sync(0xffffffffu, r2, d);
        r3 += __shfl_xor_sync(0xffffffffu, r3, d);
    }
    if (q == 0){
        float* pp = g_pooled + b * NP + rowbase + gid;
        pp[0]  = r0 * (1.0f/16.0f);
        pp[8]  = r1 * (1.0f/16.0f);
        pp[16] = r2 * (1.0f/16.0f);
        pp[24] = r3 * (1.0f/16.0f);
    }
}

// =======================================================================
// Kernel 2 (fused): grid 65, 256 threads.
//   blocks 0..63: per-batch fine-grained merge -> atomicAdd g_accs, bump g_cnt
//   block 64    : contrastive + triplet, spin on g_cnt, write out[0..2]
// =======================================================================
__global__ __launch_bounds__(256)
void k_fuse(const float* __restrict__ logit_scale, const int* __restrict__ idx,
            float* __restrict__ out){
    const int lane = threadIdx.x & 31;
    const int w    = threadIdx.x >> 5;     // 0..7
    const int tid  = threadIdx.x;

    if (blockIdx.x < 64){
        const int b = blockIdx.x;
        __shared__ float s_red[8];
        __shared__ float s_sp[8];
        __shared__ float s_top[8 * 5];

        // ---- part A: per-noun lse + top5 merged over 18 chunks ----
        float contrib = 0.0f;
        #pragma unroll
        for (int mi = 0; mi < 2; ++mi){
            const int m = w + mi * 8;
            const int base = (b * MM + m) * NCHUNK;
            float mxA = (lane < NCHUNK) ? g_mx[base + lane] : -1e30f;
            float mx = mxA;
            #pragma unroll
            for (int d = 16; d >= 1; d >>= 1) mx = fmaxf(mx, __shfl_xor_sync(0xffffffffu, mx, d));
            float se = (lane < NCHUNK) ? g_se[base + lane] * __expf(mxA - mx) : 0.0f;
            #pragma unroll
            for (int d = 16; d >= 1; d >>= 1) se += __shfl_xor_sync(0xffffffffu, se, d);

            float t[5] = {-1e30f, -1e30f, -1e30f, -1e30f, -1e30f};
            if (lane < NCHUNK){
                #pragma unroll
                for (int i = 0; i < 5; ++i) top5_insert(t, g_t5[(base + lane)*5 + i]);
            }
            float tsum = warp_top5_sum(t, lane, nullptr);
            contrib += 5.0f * (mx + __logf(se)) - tsum;
        }
        if (lane == 0) s_red[w] = contrib;

        // ---- part B: pooled softplus sum + top5 over 576 ----
        float u[5] = {-1e30f, -1e30f, -1e30f, -1e30f, -1e30f};
        float sp = 0.0f;
        for (int n = tid; n < NP; n += 256){
            float x = g_pooled[b * NP + n];
            sp += fmaxf(x, 0.0f) + __logf(1.0f + __expf(-fabsf(x)));
            top5_insert(u, x);
        }
        #pragma unroll
        for (int d = 16; d >= 1; d >>= 1) sp += __shfl_xor_sync(0xffffffffu, sp, d);
        if (lane == 0) s_sp[w] = sp;
        warp_top5_sum(u, lane, &s_top[w * 5]);
        __syncthreads();

        if (w == 0){
            float qq[5] = {-1e30f, -1e30f, -1e30f, -1e30f, -1e30f};
            if (lane < 40) top5_insert(qq, s_top[lane]);
            if (lane < 8)  top5_insert(qq, s_top[lane + 32]);
            float ftop = warp_top5_sum(qq, lane, nullptr);

            float spt = (lane < 8) ? s_sp[lane] : 0.0f;
            float crt = (lane < 8) ? s_red[lane] : 0.0f;
            #pragma unroll
            for (int d = 16; d >= 1; d >>= 1){
                spt += __shfl_xor_sync(0xffffffffu, spt, d);
                crt += __shfl_xor_sync(0xffffffffu, crt, d);
            }
            if (lane == 0){
                atomicAdd(&g_accs[0], (double)crt);
                atomicAdd(&g_accs[1], (double)(spt - ftop));
                __threadfence();
                atomicAdd(&g_cnt, 1u);
            }
        }
        return;
    }

    // ---------------- block 64: contrastive + triplet + combine ----------------
    __shared__ float sc[64][65];
    __shared__ int   sidx[64];
    __shared__ float redc[8];
    __shared__ float redt[8];

    #pragma unroll
    for (int e = tid; e < 4096; e += 256) sc[e >> 6][e & 63] = g_scores[e];
    if (tid < 64) sidx[tid] = idx[tid];
    __syncthreads();

    const float s = logit_scale[0];

    float contrib = 0.0f;
    #pragma unroll
    for (int rr = 0; rr < 8; ++rr){
        const int r = w * 8 + rr;
        const int myid = sidx[r];
        const int m0 = (sidx[lane]      == myid);
        const int m1 = (sidx[lane + 32] == myid);

        float a0 = s * sc[r][lane], a1 = s * sc[r][lane + 32];
        float mx = fmaxf(a0, a1);
        #pragma unroll
        for (int d = 16; d >= 1; d >>= 1) mx = fmaxf(mx, __shfl_xor_sync(0xffffffffu, mx, d));
        float se   = __expf(a0 - mx) + __expf(a1 - mx);
        float ms   = (m0 ? a0 : 0.0f) + (m1 ? a1 : 0.0f);
        float cntf = (float)(m0 + m1);
        #pragma unroll
        for (int d = 16; d >= 1; d >>= 1){
            se   += __shfl_xor_sync(0xffffffffu, se,   d);
            ms   += __shfl_xor_sync(0xffffffffu, ms,   d);
            cntf += __shfl_xor_sync(0xffffffffu, cntf, d);
        }
        float li2t = mx + __logf(se) - ms / cntf;

        float b0 = s * sc[lane][r], b1 = s * sc[lane + 32][r];
        float mxc = fmaxf(b0, b1);
        #pragma unroll
        for (int d = 16; d >= 1; d >>= 1) mxc = fmaxf(mxc, __shfl_xor_sync(0xffffffffu, mxc, d));
        float sec = __expf(b0 - mxc) + __expf(b1 - mxc);
        float ms2 = (m0 ? b0 : 0.0f) + (m1 ? b1 : 0.0f);
        #pragma unroll
        for (int d = 16; d >= 1; d >>= 1){
            sec += __shfl_xor_sync(0xffffffffu, sec, d);
            ms2 += __shfl_xor_sync(0xffffffffu, ms2, d);
        }
        float lt2i = mxc + __logf(sec) - ms2 / cntf;

        contrib += 0.5f * (li2t + lt2i);
    }
    if (lane == 0) redc[w] = contrib;

    float mt = 0.0f;
    #pragma unroll
    for (int e = tid; e < 4096; e += 256){
        int i = e >> 6, j = e & 63;
        if (i != j){
            float v = sc[i][j];
            mt += fmaxf(0.0f, 0.1f + v - sc[i][i]) + fmaxf(0.0f, 0.1f + v - sc[j][j]);
        }
    }
    #pragma unroll
    for (int d = 16; d >= 1; d >>= 1) mt += __shfl_xor_sync(0xffffffffu, mt, d);
    if (lane == 0) redt[w] = mt;
    __syncthreads();

    if (w == 0){
        float c = (lane < 8) ? redc[lane] : 0.0f;
        float t = (lane < 8) ? redt[lane] : 0.0f;
        #pragma unroll
        for (int d = 16; d >= 1; d >>= 1){
            c += __shfl_xor_sync(0xffffffffu, c, d);
            t += __shfl_xor_sync(0xffffffffu, t, d);
        }
        if (lane == 0){
            // wait for the 64 fine-merge blocks
            while (atomicAdd(&g_cnt, 0u) < 64u) __nanosleep(64);
            __threadfence();
            out[0] = c / 64.0f;
            out[1] = 0.5f * t;
            double contrast = g_accs[0] / (double)(BB * MM);
            double mask     = g_accs[1] / (double)(BB * NP);
            out[2] = (float)(0.6 * contrast + 0.4 * mask);
        }
    }
}

// =======================================================================
extern "C" void kernel_launch(void* const* d_in, const int* in_sizes, int n_in,
                              void* d_out, int out_size){
    (void)in_sizes; (void)n_in; (void)out_size;
    const float* patch = (const float*)d_in[0];
    const float* noun  = (const float*)d_in[1];
    const float* img   = (const float*)d_in[2];
    const float* txt   = (const float*)d_in[3];
    const float* lsc   = (const float*)d_in[4];
    const int*   idx   = (const int*)d_in[5];
    float* out = (float*)d_out;

    dim3 gsim(4, 64);
    k_sim<<<gsim, 192>>>(patch, noun, img, txt);
    k_fuse<<<65, 256>>>(lsc, idx, out);
}